// round 6
// baseline (speedup 1.0000x reference)
#include <cuda_runtime.h>
#include <cuda_bf16.h>
#include <cstdint>

#define N_NODES 100000
#define HID     128
#define N_EDGES 1600000
#define NSCAN_BLOCKS 98   // 98*1024 = 100352 >= N_NODES
#define NE4 (N_EDGES / 4) // 400000 int4 elements

// Scratch (__device__ globals; no allocation allowed)
__device__ float g_SI[2u * N_NODES * HID];     // [0]=S, [1]=I  (102.4 MB)
__device__ int   g_cnt[N_NODES];               // histogram, then bucket cursor
__device__ int   g_start[N_NODES];             // exclusive prefix (row segment start)
__device__ int   g_blk[1024];                  // block sums for scan
__device__ int   g_scols[N_EDGES];             // cols sorted by destination row

// ---------------------------------------------------------------------------
// packed fp32x2 FMA (Blackwell FFMA2 — only reachable via PTX)
// ---------------------------------------------------------------------------
__device__ __forceinline__ void fma_f32x2(unsigned long long& d,
                                          unsigned long long a,
                                          unsigned long long b) {
    asm("fma.rn.f32x2 %0, %1, %2, %3;" : "=l"(d) : "l"(a), "l"(b), "l"(d));
}

// ---------------------------------------------------------------------------
// Kernel: S/I = sigmoid(x[s] @ W^T + b), s in {0,1}
// 128x128 block tile, 256 threads, 8x8 per-thread regs, f32x2 on k.
// ---------------------------------------------------------------------------
#define WPAD 130
__global__ void __launch_bounds__(256, 1)
gemm_sigmoid_kernel(const float* __restrict__ x,
                    const float* __restrict__ W,
                    const float* __restrict__ b) {
    extern __shared__ float sm[];
    float* Xs = sm;                     // 128*128
    float* Ws = sm + 128 * 128;         // 128*WPAD, layout [c][k]
    float* Bs = Ws + 128 * WPAD;        // 128

    const int s    = blockIdx.y;
    const int row0 = blockIdx.x * 128;
    const int tid  = threadIdx.x;

    for (int idx = tid; idx < 128 * 128; idx += 256) {
        int c = idx >> 7, k = idx & 127;
        Ws[c * WPAD + k] = W[idx];
    }
    if (tid < 128) Bs[tid] = b[tid];

    const float4* xs4 = (const float4*)(x + ((size_t)s * N_NODES + row0) * HID);
    for (int idx = tid; idx < 128 * 32; idx += 256)
        ((float4*)Xs)[idx] = xs4[idx];
    __syncthreads();

    const int ty = tid >> 4;       // 0..15 -> 8 rows each
    const int tx = tid & 15;       // 0..15 -> cols tx + 16*j

    unsigned long long acc[8][8];
#pragma unroll
    for (int i = 0; i < 8; i++)
#pragma unroll
        for (int j = 0; j < 8; j++) acc[i][j] = 0ull;

#pragma unroll 4
    for (int k = 0; k < 128; k += 2) {
        unsigned long long xv[8], wv[8];
#pragma unroll
        for (int i = 0; i < 8; i++)
            xv[i] = *(const unsigned long long*)(Xs + (ty * 8 + i) * 128 + k);
#pragma unroll
        for (int j = 0; j < 8; j++)
            wv[j] = *(const unsigned long long*)(Ws + (tx + 16 * j) * WPAD + k);
#pragma unroll
        for (int j = 0; j < 8; j++)
#pragma unroll
            for (int i = 0; i < 8; i++)
                fma_f32x2(acc[i][j], xv[i], wv[j]);
    }

    float* outS = g_SI + ((size_t)s * N_NODES + row0) * HID;
#pragma unroll
    for (int i = 0; i < 8; i++) {
        int r = ty * 8 + i;
        if (row0 + r < N_NODES) {
#pragma unroll
            for (int j = 0; j < 8; j++) {
                int c = tx + 16 * j;
                unsigned long long a = acc[i][j];
                float lo = __uint_as_float((unsigned)(a & 0xffffffffull));
                float hi = __uint_as_float((unsigned)(a >> 32));
                float z  = lo + hi + Bs[c];
                outS[(size_t)r * HID + c] = 1.f / (1.f + __expf(-z));
            }
        }
    }
}

// ---------------------------------------------------------------------------
// Counting sort of edges by destination row
// ---------------------------------------------------------------------------
__global__ void __launch_bounds__(1024) zero_cnt_kernel() {
    int i = blockIdx.x * 1024 + threadIdx.x;
    if (i < N_NODES) g_cnt[i] = 0;
}

__global__ void __launch_bounds__(256) hist_kernel(const int* __restrict__ rows) {
    int t = blockIdx.x * 256 + threadIdx.x;
    if (t >= NE4) return;
    int4 r = ((const int4*)rows)[t];
    atomicAdd(&g_cnt[r.x], 1);
    atomicAdd(&g_cnt[r.y], 1);
    atomicAdd(&g_cnt[r.z], 1);
    atomicAdd(&g_cnt[r.w], 1);
}

__global__ void __launch_bounds__(1024) scan1_kernel() {
    __shared__ int sh[1024];
    int tid = threadIdx.x;
    int i   = blockIdx.x * 1024 + tid;
    int v   = (i < N_NODES) ? g_cnt[i] : 0;
    sh[tid] = v;
    __syncthreads();
#pragma unroll
    for (int off = 1; off < 1024; off <<= 1) {
        int t = (tid >= off) ? sh[tid - off] : 0;
        __syncthreads();
        sh[tid] += t;
        __syncthreads();
    }
    if (i < N_NODES) g_start[i] = sh[tid] - v;   // exclusive
    if (tid == 1023) g_blk[blockIdx.x] = sh[1023];
}

__global__ void __launch_bounds__(128) scan2_kernel() {
    __shared__ int sh[128];
    int tid = threadIdx.x;
    int v   = (tid < NSCAN_BLOCKS) ? g_blk[tid] : 0;
    sh[tid] = v;
    __syncthreads();
#pragma unroll
    for (int off = 1; off < 128; off <<= 1) {
        int t = (tid >= off) ? sh[tid - off] : 0;
        __syncthreads();
        sh[tid] += t;
        __syncthreads();
    }
    g_blk[tid] = sh[tid] - v;   // exclusive
}

__global__ void __launch_bounds__(1024) scan3_kernel() {
    int i = blockIdx.x * 1024 + threadIdx.x;
    if (i < N_NODES) {
        int s = g_start[i] + g_blk[i >> 10];
        g_start[i] = s;
        g_cnt[i]   = s;          // bucket cursor
    }
}

__global__ void __launch_bounds__(256)
bucket_kernel(const int* __restrict__ rows, const int* __restrict__ cols) {
    int t = blockIdx.x * 256 + threadIdx.x;
    if (t >= NE4) return;
    int4 r = ((const int4*)rows)[t];
    int4 c = ((const int4*)cols)[t];
    int p0 = atomicAdd(&g_cnt[r.x], 1);
    int p1 = atomicAdd(&g_cnt[r.y], 1);
    int p2 = atomicAdd(&g_cnt[r.z], 1);
    int p3 = atomicAdd(&g_cnt[r.w], 1);
    g_scols[p0] = c.x;
    g_scols[p1] = c.y;
    g_scols[p2] = c.z;
    g_scols[p3] = c.w;
}

// ---------------------------------------------------------------------------
// Fused gather + epilogue: one warp per row, high-MLP gather.
//   Indices for the whole segment (<=32 typical) are loaded by ONE coalesced
//   LDG (lane l -> edge s0+l), then broadcast via shfl. Four independent
//   float4 accumulators keep >=4 gathers in flight (L2-latency amortization).
// ---------------------------------------------------------------------------
__global__ void __launch_bounds__(256)
gather_epilogue_kernel(const float* __restrict__ x, float* __restrict__ out) {
    const int warp = (blockIdx.x * 256 + threadIdx.x) >> 5;
    const int lane = threadIdx.x & 31;
    if (warp >= N_NODES) return;
    const int row = warp;

    const int s0   = g_start[row];
    const int s1   = (row + 1 < N_NODES) ? g_start[row + 1] : N_EDGES;
    const int cnt  = s1 - s0;
    const int cmax = cnt < 32 ? cnt : 32;

    // One coalesced index load covers the whole typical segment.
    int c_l = 0;
    if (lane < cmax) c_l = g_scols[s0 + lane];

    const float4* I4 = (const float4*)(g_SI + (size_t)N_NODES * HID);
    float4 a0 = make_float4(0.f, 0.f, 0.f, 0.f);
    float4 a1 = make_float4(0.f, 0.f, 0.f, 0.f);
    float4 a2 = make_float4(0.f, 0.f, 0.f, 0.f);
    float4 a3 = make_float4(0.f, 0.f, 0.f, 0.f);

    int i = 0;
    for (; i + 4 <= cmax; i += 4) {
        int c0 = __shfl_sync(0xffffffffu, c_l, i);
        int c1 = __shfl_sync(0xffffffffu, c_l, i + 1);
        int c2 = __shfl_sync(0xffffffffu, c_l, i + 2);
        int c3 = __shfl_sync(0xffffffffu, c_l, i + 3);
        float4 v0 = I4[(size_t)c0 * 32 + lane];
        float4 v1 = I4[(size_t)c1 * 32 + lane];
        float4 v2 = I4[(size_t)c2 * 32 + lane];
        float4 v3 = I4[(size_t)c3 * 32 + lane];
        a0.x += v0.x; a0.y += v0.y; a0.z += v0.z; a0.w += v0.w;
        a1.x += v1.x; a1.y += v1.y; a1.z += v1.z; a1.w += v1.w;
        a2.x += v2.x; a2.y += v2.y; a2.z += v2.z; a2.w += v2.w;
        a3.x += v3.x; a3.y += v3.y; a3.z += v3.z; a3.w += v3.w;
    }
    for (; i < cmax; i++) {
        int c0 = __shfl_sync(0xffffffffu, c_l, i);
        float4 v0 = I4[(size_t)c0 * 32 + lane];
        a0.x += v0.x; a0.y += v0.y; a0.z += v0.z; a0.w += v0.w;
    }
    // Rare tail: segments longer than 32 (Poisson(16), P ~ 1e-4).
    for (i = 32; i < cnt; i++) {
        int c0 = g_scols[s0 + i];        // uniform broadcast load
        float4 v0 = I4[(size_t)c0 * 32 + lane];
        a0.x += v0.x; a0.y += v0.y; a0.z += v0.z; a0.w += v0.w;
    }

    float4 AI;
    AI.x = (a0.x + a1.x) + (a2.x + a3.x);
    AI.y = (a0.y + a1.y) + (a2.y + a3.y);
    AI.z = (a0.z + a1.z) + (a2.z + a3.z);
    AI.w = (a0.w + a1.w) + (a2.w + a3.w);

    const float beta  = x[((size_t)3 * N_NODES + row) * HID + 0];
    const float gamma = x[((size_t)3 * N_NODES + row) * HID + 1];

    const size_t base = (size_t)row * 32 + lane;
    float4 S = ((const float4*)g_SI)[base];
    float4 I = I4[base];

    float4 dS, dI, dR;
    dS.x = -beta * AI.x * S.x;  dS.y = -beta * AI.y * S.y;
    dS.z = -beta * AI.z * S.z;  dS.w = -beta * AI.w * S.w;
    dI.x = -dS.x - gamma * I.x; dI.y = -dS.y - gamma * I.y;
    dI.z = -dS.z - gamma * I.z; dI.w = -dS.w - gamma * I.w;
    dR.x =  gamma * I.x;        dR.y =  gamma * I.y;
    dR.z =  gamma * I.z;        dR.w =  gamma * I.w;

    float4* o = (float4*)out;
    const size_t slab = (size_t)N_NODES * 32;
    o[base]            = dS;
    o[slab + base]     = dI;
    o[2 * slab + base] = dR;
    o[3 * slab + base] = make_float4(0.f, 0.f, 0.f, 0.f);
}

// ---------------------------------------------------------------------------
extern "C" void kernel_launch(void* const* d_in, const int* in_sizes, int n_in,
                              void* d_out, int out_size) {
    const float* x    = (const float*)d_in[0];
    const float* W    = (const float*)d_in[1];
    const float* b    = (const float*)d_in[2];
    const int*   rows = (const int*)d_in[3];
    const int*   cols = (const int*)d_in[4];
    float*       out  = (float*)d_out;

    const int smem = (128 * 128 + 128 * WPAD + 128) * 4;   // 132608 B
    cudaFuncSetAttribute(gemm_sigmoid_kernel,
                         cudaFuncAttributeMaxDynamicSharedMemorySize, smem);

    // GEMM first (S/I needed by the final kernel only).
    dim3 ggrid((N_NODES + 127) / 128, 2);
    gemm_sigmoid_kernel<<<ggrid, 256, smem>>>(x, W, b);

    // Counting sort of edges by destination row (indices only).
    const int ebloks = (NE4 + 255) / 256;       // full edge coverage
    zero_cnt_kernel<<<NSCAN_BLOCKS, 1024>>>();
    hist_kernel<<<ebloks, 256>>>(rows);
    scan1_kernel<<<NSCAN_BLOCKS, 1024>>>();
    scan2_kernel<<<1, 128>>>();
    scan3_kernel<<<NSCAN_BLOCKS, 1024>>>();
    bucket_kernel<<<ebloks, 256>>>(rows, cols);

    // Fused gather (register accumulation, no atomics) + epilogue.
    gather_epilogue_kernel<<<(N_NODES + 7) / 8, 256>>>(x, out);
}

// round 8
// speedup vs baseline: 1.4151x; 1.4151x over previous
#include <cuda_runtime.h>
#include <cuda_bf16.h>
#include <cstdint>

#define N_NODES 100000
#define HID     128
#define N_EDGES 1600000
#define NSCAN_BLOCKS 98   // 98*1024 = 100352 >= N_NODES
#define NE4 (N_EDGES / 4) // 400000 int4 elements
#define TILES   782       // ceil(100000/128)
#define NJOBS   (2 * TILES)
#define GEMM_GRID 148

// Scratch (__device__ globals; no allocation allowed)
__device__ float g_SI[2u * N_NODES * HID];     // [0]=S, [1]=I  (102.4 MB)
__device__ int   g_cnt[N_NODES];               // histogram, then bucket cursor
__device__ int   g_start[N_NODES];             // exclusive prefix (row segment start)
__device__ int   g_blk[1024];                  // block sums for scan
__device__ int   g_scols[N_EDGES];             // cols sorted by destination row

// ---------------------------------------------------------------------------
// packed fp32x2 FMA (Blackwell FFMA2 — only reachable via PTX)
// ---------------------------------------------------------------------------
__device__ __forceinline__ void fma_f32x2(unsigned long long& d,
                                          unsigned long long a,
                                          unsigned long long b) {
    asm("fma.rn.f32x2 %0, %1, %2, %3;" : "=l"(d) : "l"(a), "l"(b), "l"(d));
}

__device__ __forceinline__ unsigned smem_u32(const void* p) {
    unsigned a;
    asm("{ .reg .u64 t; cvta.to.shared.u64 t, %1; cvt.u32.u64 %0, t; }"
        : "=r"(a) : "l"(p));
    return a;
}

// ---------------------------------------------------------------------------
// Persistent GEMM: S/I = sigmoid(x[s] @ W^T + b), s in {0,1}
// 148 blocks, each loops tile-jobs. W/b in SMEM once. X double-buffered via
// cp.async so tile loads hide under the FFMA2 mainloop (~91us chip floor).
// SMEM: Ws[128*WPAD] + Xs0[128*128] + Xs1[128*128] + Bs[128] = 198144 B.
// ---------------------------------------------------------------------------
#define WPAD 130
__global__ void __launch_bounds__(256, 1)
gemm_persistent_kernel(const float* __restrict__ x,
                       const float* __restrict__ W,
                       const float* __restrict__ b) {
    extern __shared__ float sm[];
    float* Ws  = sm;                          // 128*WPAD
    float* Xs0 = sm + 128 * WPAD;             // 16384
    float* Xs1 = Xs0 + 128 * 128;             // 16384
    float* Bs  = Xs1 + 128 * 128;             // 128

    const int tid = threadIdx.x;

    // Load W (as Ws[c][k]) and b once per block.
    for (int idx = tid; idx < 128 * 128; idx += 256) {
        int c = idx >> 7, k = idx & 127;
        Ws[c * WPAD + k] = W[idx];
    }
    if (tid < 128) Bs[tid] = b[tid];

    const int ty = tid >> 4;       // 0..15 -> 8 rows each
    const int tx = tid & 15;       // 0..15 -> cols tx + 16*j

    // Prefetch helper: 128 rows x 512 B = 4096 16B chunks, 16 per thread.
    auto issue_tile = [&](int job, float* dst) {
        const int s    = (job >= TILES) ? 1 : 0;
        const int row0 = (job - s * TILES) * 128;
        const char* src = (const char*)(x + ((size_t)s * N_NODES + row0) * HID);
        unsigned d = smem_u32(dst);
#pragma unroll
        for (int i = 0; i < 16; i++) {
            int c = tid + i * 256;
            asm volatile("cp.async.cg.shared.global [%0], [%1], 16;"
                         :: "r"(d + c * 16), "l"(src + (size_t)c * 16) : "memory");
        }
        asm volatile("cp.async.commit_group;" ::: "memory");
    };

    int job = blockIdx.x;
    if (job < NJOBS) issue_tile(job, Xs0);
    int buf = 0;

    for (; job < NJOBS; job += GEMM_GRID) {
        const int nxt = job + GEMM_GRID;
        float* Xc = buf ? Xs1 : Xs0;
        if (nxt < NJOBS) {
            issue_tile(nxt, buf ? Xs0 : Xs1);
            asm volatile("cp.async.wait_group 1;" ::: "memory");
        } else {
            asm volatile("cp.async.wait_group 0;" ::: "memory");
        }
        __syncthreads();

        unsigned long long acc[8][8];
#pragma unroll
        for (int i = 0; i < 8; i++)
#pragma unroll
            for (int j = 0; j < 8; j++) acc[i][j] = 0ull;

#pragma unroll 4
        for (int k = 0; k < 128; k += 2) {
            unsigned long long xv[8], wv[8];
#pragma unroll
            for (int i = 0; i < 8; i++)
                xv[i] = *(const unsigned long long*)(Xc + (ty * 8 + i) * 128 + k);
#pragma unroll
            for (int j = 0; j < 8; j++)
                wv[j] = *(const unsigned long long*)(Ws + (tx + 16 * j) * WPAD + k);
#pragma unroll
            for (int j = 0; j < 8; j++)
#pragma unroll
                for (int i = 0; i < 8; i++)
                    fma_f32x2(acc[i][j], xv[i], wv[j]);
        }

        const int s    = (job >= TILES) ? 1 : 0;
        const int row0 = (job - s * TILES) * 128;
        float* outS = g_SI + ((size_t)s * N_NODES + row0) * HID;
#pragma unroll
        for (int i = 0; i < 8; i++) {
            int r = ty * 8 + i;
            if (row0 + r < N_NODES) {
#pragma unroll
                for (int j = 0; j < 8; j++) {
                    int c = tx + 16 * j;
                    unsigned long long a = acc[i][j];
                    float lo = __uint_as_float((unsigned)(a & 0xffffffffull));
                    float hi = __uint_as_float((unsigned)(a >> 32));
                    float z  = lo + hi + Bs[c];
                    outS[(size_t)r * HID + c] = 1.f / (1.f + __expf(-z));
                }
            }
        }
        __syncthreads();    // protect Xc before it is refilled next iteration
        buf ^= 1;
    }
}

// ---------------------------------------------------------------------------
// Counting sort of edges by destination row
// ---------------------------------------------------------------------------
__global__ void __launch_bounds__(1024) zero_cnt_kernel() {
    int i = blockIdx.x * 1024 + threadIdx.x;
    if (i < N_NODES) g_cnt[i] = 0;
}

__global__ void __launch_bounds__(256) hist_kernel(const int* __restrict__ rows) {
    int t = blockIdx.x * 256 + threadIdx.x;
    if (t >= NE4) return;
    int4 r = ((const int4*)rows)[t];
    atomicAdd(&g_cnt[r.x], 1);
    atomicAdd(&g_cnt[r.y], 1);
    atomicAdd(&g_cnt[r.z], 1);
    atomicAdd(&g_cnt[r.w], 1);
}

__global__ void __launch_bounds__(1024) scan1_kernel() {
    __shared__ int sh[1024];
    int tid = threadIdx.x;
    int i   = blockIdx.x * 1024 + tid;
    int v   = (i < N_NODES) ? g_cnt[i] : 0;
    sh[tid] = v;
    __syncthreads();
#pragma unroll
    for (int off = 1; off < 1024; off <<= 1) {
        int t = (tid >= off) ? sh[tid - off] : 0;
        __syncthreads();
        sh[tid] += t;
        __syncthreads();
    }
    if (i < N_NODES) g_start[i] = sh[tid] - v;   // exclusive
    if (tid == 1023) g_blk[blockIdx.x] = sh[1023];
}

__global__ void __launch_bounds__(128) scan2_kernel() {
    __shared__ int sh[128];
    int tid = threadIdx.x;
    int v   = (tid < NSCAN_BLOCKS) ? g_blk[tid] : 0;
    sh[tid] = v;
    __syncthreads();
#pragma unroll
    for (int off = 1; off < 128; off <<= 1) {
        int t = (tid >= off) ? sh[tid - off] : 0;
        __syncthreads();
        sh[tid] += t;
        __syncthreads();
    }
    g_blk[tid] = sh[tid] - v;   // exclusive
}

__global__ void __launch_bounds__(1024) scan3_kernel() {
    int i = blockIdx.x * 1024 + threadIdx.x;
    if (i < N_NODES) {
        int s = g_start[i] + g_blk[i >> 10];
        g_start[i] = s;
        g_cnt[i]   = s;          // bucket cursor
    }
}

__global__ void __launch_bounds__(256)
bucket_kernel(const int* __restrict__ rows, const int* __restrict__ cols) {
    int t = blockIdx.x * 256 + threadIdx.x;
    if (t >= NE4) return;
    int4 r = ((const int4*)rows)[t];
    int4 c = ((const int4*)cols)[t];
    int p0 = atomicAdd(&g_cnt[r.x], 1);
    int p1 = atomicAdd(&g_cnt[r.y], 1);
    int p2 = atomicAdd(&g_cnt[r.z], 1);
    int p3 = atomicAdd(&g_cnt[r.w], 1);
    g_scols[p0] = c.x;
    g_scols[p1] = c.y;
    g_scols[p2] = c.z;
    g_scols[p3] = c.w;
}

// ---------------------------------------------------------------------------
// Fused gather + epilogue: one warp per row (R5 form — proven fastest).
// ---------------------------------------------------------------------------
__global__ void __launch_bounds__(256)
gather_epilogue_kernel(const float* __restrict__ x, float* __restrict__ out) {
    const int warp = (blockIdx.x * 256 + threadIdx.x) >> 5;
    const int lane = threadIdx.x & 31;
    if (warp >= N_NODES) return;
    const int row = warp;

    const int s0 = g_start[row];
    const int s1 = (row + 1 < N_NODES) ? g_start[row + 1] : N_EDGES;

    const float4* I4 = (const float4*)(g_SI + (size_t)N_NODES * HID);
    float4 a0 = make_float4(0.f, 0.f, 0.f, 0.f);
    float4 a1 = make_float4(0.f, 0.f, 0.f, 0.f);

    int i = s0;
    for (; i + 1 < s1; i += 2) {
        int c0 = g_scols[i];
        int c1 = g_scols[i + 1];
        float4 v0 = I4[(size_t)c0 * 32 + lane];
        float4 v1 = I4[(size_t)c1 * 32 + lane];
        a0.x += v0.x; a0.y += v0.y; a0.z += v0.z; a0.w += v0.w;
        a1.x += v1.x; a1.y += v1.y; a1.z += v1.z; a1.w += v1.w;
    }
    if (i < s1) {
        int c0 = g_scols[i];
        float4 v0 = I4[(size_t)c0 * 32 + lane];
        a0.x += v0.x; a0.y += v0.y; a0.z += v0.z; a0.w += v0.w;
    }
    float4 AI;
    AI.x = a0.x + a1.x; AI.y = a0.y + a1.y;
    AI.z = a0.z + a1.z; AI.w = a0.w + a1.w;

    const float beta  = x[((size_t)3 * N_NODES + row) * HID + 0];
    const float gamma = x[((size_t)3 * N_NODES + row) * HID + 1];

    const size_t base = (size_t)row * 32 + lane;
    float4 S = ((const float4*)g_SI)[base];
    float4 I = I4[base];

    float4 dS, dI, dR;
    dS.x = -beta * AI.x * S.x;  dS.y = -beta * AI.y * S.y;
    dS.z = -beta * AI.z * S.z;  dS.w = -beta * AI.w * S.w;
    dI.x = -dS.x - gamma * I.x; dI.y = -dS.y - gamma * I.y;
    dI.z = -dS.z - gamma * I.z; dI.w = -dS.w - gamma * I.w;
    dR.x =  gamma * I.x;        dR.y =  gamma * I.y;
    dR.z =  gamma * I.z;        dR.w =  gamma * I.w;

    float4* o = (float4*)out;
    const size_t slab = (size_t)N_NODES * 32;
    o[base]            = dS;
    o[slab + base]     = dI;
    o[2 * slab + base] = dR;
    o[3 * slab + base] = make_float4(0.f, 0.f, 0.f, 0.f);
}

// ---------------------------------------------------------------------------
extern "C" void kernel_launch(void* const* d_in, const int* in_sizes, int n_in,
                              void* d_out, int out_size) {
    const float* x    = (const float*)d_in[0];
    const float* W    = (const float*)d_in[1];
    const float* b    = (const float*)d_in[2];
    const int*   rows = (const int*)d_in[3];
    const int*   cols = (const int*)d_in[4];
    float*       out  = (float*)d_out;

    const int smem = (128 * WPAD + 2 * 128 * 128 + 128) * 4;   // 198144 B
    cudaFuncSetAttribute(gemm_persistent_kernel,
                         cudaFuncAttributeMaxDynamicSharedMemorySize, smem);

    // Persistent GEMM (W in SMEM once, X double-buffered via cp.async).
    gemm_persistent_kernel<<<GEMM_GRID, 256, smem>>>(x, W, b);

    // Counting sort of edges by destination row (indices only).
    const int ebloks = (NE4 + 255) / 256;       // full edge coverage
    zero_cnt_kernel<<<NSCAN_BLOCKS, 1024>>>();
    hist_kernel<<<ebloks, 256>>>(rows);
    scan1_kernel<<<NSCAN_BLOCKS, 1024>>>();
    scan2_kernel<<<1, 128>>>();
    scan3_kernel<<<NSCAN_BLOCKS, 1024>>>();
    bucket_kernel<<<ebloks, 256>>>(rows, cols);

    // Fused gather (register accumulation, no atomics) + epilogue.
    gather_epilogue_kernel<<<(N_NODES + 7) / 8, 256>>>(x, out);
}

// round 9
// speedup vs baseline: 1.5467x; 1.0930x over previous
#include <cuda_runtime.h>
#include <cuda_bf16.h>
#include <cstdint>

#define N_NODES 100000
#define HID     128
#define N_EDGES 1600000
#define NSCAN_BLOCKS 98   // 98*1024 = 100352 >= N_NODES
#define NE4 (N_EDGES / 4) // 400000 int4 elements
#define TILES   782       // ceil(100000/128)
#define NJOBS   (2 * TILES)
#define GEMM_GRID 148

// Scratch (__device__ globals; no allocation allowed)
__device__ float g_SI[2u * N_NODES * HID];     // [0]=S, [1]=I  (102.4 MB)
__device__ int   g_cnt[N_NODES];               // histogram, then bucket cursor
__device__ int   g_start[N_NODES];             // exclusive prefix (row segment start)
__device__ int   g_blk[1024];                  // block sums for scan
__device__ int   g_scols[N_EDGES];             // cols sorted by destination row

// ---------------------------------------------------------------------------
// packed fp32x2 FMA (Blackwell FFMA2 — only reachable via PTX)
// ---------------------------------------------------------------------------
__device__ __forceinline__ void fma_f32x2(unsigned long long& d,
                                          unsigned long long a,
                                          unsigned long long b) {
    asm("fma.rn.f32x2 %0, %1, %2, %3;" : "=l"(d) : "l"(a), "l"(b), "l"(d));
}

__device__ __forceinline__ unsigned smem_u32(const void* p) {
    unsigned a;
    asm("{ .reg .u64 t; cvta.to.shared.u64 t, %1; cvt.u32.u64 %0, t; }"
        : "=r"(a) : "l"(p));
    return a;
}

// ---------------------------------------------------------------------------
// Persistent GEMM: S/I = sigmoid(x[s] @ W^T + b), s in {0,1}
// 148 blocks loop over tile-jobs; W/b in SMEM once; X double-buffered via
// cp.async. SMEM = 198144 B.
// ---------------------------------------------------------------------------
#define WPAD 130
__global__ void __launch_bounds__(256, 1)
gemm_persistent_kernel(const float* __restrict__ x,
                       const float* __restrict__ W,
                       const float* __restrict__ b) {
    extern __shared__ float sm[];
    float* Ws  = sm;                          // 128*WPAD
    float* Xs0 = sm + 128 * WPAD;             // 16384
    float* Xs1 = Xs0 + 128 * 128;             // 16384
    float* Bs  = Xs1 + 128 * 128;             // 128

    const int tid = threadIdx.x;

    for (int idx = tid; idx < 128 * 128; idx += 256) {
        int c = idx >> 7, k = idx & 127;
        Ws[c * WPAD + k] = W[idx];
    }
    if (tid < 128) Bs[tid] = b[tid];

    const int ty = tid >> 4;       // 0..15 -> 8 rows each
    const int tx = tid & 15;       // 0..15 -> cols tx + 16*j

    auto issue_tile = [&](int job, float* dst) {
        const int s    = (job >= TILES) ? 1 : 0;
        const int row0 = (job - s * TILES) * 128;
        const char* src = (const char*)(x + ((size_t)s * N_NODES + row0) * HID);
        unsigned d = smem_u32(dst);
#pragma unroll
        for (int i = 0; i < 16; i++) {
            int c = tid + i * 256;
            asm volatile("cp.async.cg.shared.global [%0], [%1], 16;"
                         :: "r"(d + c * 16), "l"(src + (size_t)c * 16) : "memory");
        }
        asm volatile("cp.async.commit_group;" ::: "memory");
    };

    int job = blockIdx.x;
    if (job < NJOBS) issue_tile(job, Xs0);
    int buf = 0;

    for (; job < NJOBS; job += GEMM_GRID) {
        const int nxt = job + GEMM_GRID;
        float* Xc = buf ? Xs1 : Xs0;
        if (nxt < NJOBS) {
            issue_tile(nxt, buf ? Xs0 : Xs1);
            asm volatile("cp.async.wait_group 1;" ::: "memory");
        } else {
            asm volatile("cp.async.wait_group 0;" ::: "memory");
        }
        __syncthreads();

        unsigned long long acc[8][8];
#pragma unroll
        for (int i = 0; i < 8; i++)
#pragma unroll
            for (int j = 0; j < 8; j++) acc[i][j] = 0ull;

#pragma unroll 4
        for (int k = 0; k < 128; k += 2) {
            unsigned long long xv[8], wv[8];
#pragma unroll
            for (int i = 0; i < 8; i++)
                xv[i] = *(const unsigned long long*)(Xc + (ty * 8 + i) * 128 + k);
#pragma unroll
            for (int j = 0; j < 8; j++)
                wv[j] = *(const unsigned long long*)(Ws + (tx + 16 * j) * WPAD + k);
#pragma unroll
            for (int j = 0; j < 8; j++)
#pragma unroll
                for (int i = 0; i < 8; i++)
                    fma_f32x2(acc[i][j], xv[i], wv[j]);
        }

        const int s    = (job >= TILES) ? 1 : 0;
        const int row0 = (job - s * TILES) * 128;
        float* outS = g_SI + ((size_t)s * N_NODES + row0) * HID;
#pragma unroll
        for (int i = 0; i < 8; i++) {
            int r = ty * 8 + i;
            if (row0 + r < N_NODES) {
#pragma unroll
                for (int j = 0; j < 8; j++) {
                    int c = tx + 16 * j;
                    unsigned long long a = acc[i][j];
                    float lo = __uint_as_float((unsigned)(a & 0xffffffffull));
                    float hi = __uint_as_float((unsigned)(a >> 32));
                    float z  = lo + hi + Bs[c];
                    outS[(size_t)r * HID + c] = 1.f / (1.f + __expf(-z));
                }
            }
        }
        __syncthreads();
        buf ^= 1;
    }
}

// ---------------------------------------------------------------------------
// Counting sort of edges by destination row
// ---------------------------------------------------------------------------
__global__ void __launch_bounds__(1024) zero_cnt_kernel() {
    int i = blockIdx.x * 1024 + threadIdx.x;
    if (i < N_NODES) g_cnt[i] = 0;
}

__global__ void __launch_bounds__(256) hist_kernel(const int* __restrict__ rows) {
    int t = blockIdx.x * 256 + threadIdx.x;
    if (t >= NE4) return;
    int4 r = ((const int4*)rows)[t];
    atomicAdd(&g_cnt[r.x], 1);
    atomicAdd(&g_cnt[r.y], 1);
    atomicAdd(&g_cnt[r.z], 1);
    atomicAdd(&g_cnt[r.w], 1);
}

__global__ void __launch_bounds__(1024) scan1_kernel() {
    __shared__ int sh[1024];
    int tid = threadIdx.x;
    int i   = blockIdx.x * 1024 + tid;
    int v   = (i < N_NODES) ? g_cnt[i] : 0;
    sh[tid] = v;
    __syncthreads();
#pragma unroll
    for (int off = 1; off < 1024; off <<= 1) {
        int t = (tid >= off) ? sh[tid - off] : 0;
        __syncthreads();
        sh[tid] += t;
        __syncthreads();
    }
    if (i < N_NODES) g_start[i] = sh[tid] - v;   // exclusive
    if (tid == 1023) g_blk[blockIdx.x] = sh[1023];
}

__global__ void __launch_bounds__(128) scan2_kernel() {
    __shared__ int sh[128];
    int tid = threadIdx.x;
    int v   = (tid < NSCAN_BLOCKS) ? g_blk[tid] : 0;
    sh[tid] = v;
    __syncthreads();
#pragma unroll
    for (int off = 1; off < 128; off <<= 1) {
        int t = (tid >= off) ? sh[tid - off] : 0;
        __syncthreads();
        sh[tid] += t;
        __syncthreads();
    }
    g_blk[tid] = sh[tid] - v;   // exclusive
}

__global__ void __launch_bounds__(1024) scan3_kernel() {
    int i = blockIdx.x * 1024 + threadIdx.x;
    if (i < N_NODES) {
        int s = g_start[i] + g_blk[i >> 10];
        g_start[i] = s;
        g_cnt[i]   = s;          // bucket cursor
    }
}

__global__ void __launch_bounds__(256)
bucket_kernel(const int* __restrict__ rows, const int* __restrict__ cols) {
    int t = blockIdx.x * 256 + threadIdx.x;
    if (t >= NE4) return;
    int4 r = ((const int4*)rows)[t];
    int4 c = ((const int4*)cols)[t];
    int p0 = atomicAdd(&g_cnt[r.x], 1);
    int p1 = atomicAdd(&g_cnt[r.y], 1);
    int p2 = atomicAdd(&g_cnt[r.z], 1);
    int p3 = atomicAdd(&g_cnt[r.w], 1);
    g_scols[p0] = c.x;
    g_scols[p1] = c.y;
    g_scols[p2] = c.z;
    g_scols[p3] = c.w;
}

// ---------------------------------------------------------------------------
// Fused gather + epilogue: one warp per row (R5 form).
// Output stores use .cs (evict-first) to keep the I slab L2-resident.
// ---------------------------------------------------------------------------
__global__ void __launch_bounds__(256)
gather_epilogue_kernel(const float* __restrict__ x, float* __restrict__ out) {
    const int warp = (blockIdx.x * 256 + threadIdx.x) >> 5;
    const int lane = threadIdx.x & 31;
    if (warp >= N_NODES) return;
    const int row = warp;

    const int s0 = g_start[row];
    const int s1 = (row + 1 < N_NODES) ? g_start[row + 1] : N_EDGES;

    const float4* I4 = (const float4*)(g_SI + (size_t)N_NODES * HID);
    float4 a0 = make_float4(0.f, 0.f, 0.f, 0.f);
    float4 a1 = make_float4(0.f, 0.f, 0.f, 0.f);

    int i = s0;
    for (; i + 1 < s1; i += 2) {
        int c0 = g_scols[i];
        int c1 = g_scols[i + 1];
        float4 v0 = I4[(size_t)c0 * 32 + lane];
        float4 v1 = I4[(size_t)c1 * 32 + lane];
        a0.x += v0.x; a0.y += v0.y; a0.z += v0.z; a0.w += v0.w;
        a1.x += v1.x; a1.y += v1.y; a1.z += v1.z; a1.w += v1.w;
    }
    if (i < s1) {
        int c0 = g_scols[i];
        float4 v0 = I4[(size_t)c0 * 32 + lane];
        a0.x += v0.x; a0.y += v0.y; a0.z += v0.z; a0.w += v0.w;
    }
    float4 AI;
    AI.x = a0.x + a1.x; AI.y = a0.y + a1.y;
    AI.z = a0.z + a1.z; AI.w = a0.w + a1.w;

    const float beta  = x[((size_t)3 * N_NODES + row) * HID + 0];
    const float gamma = x[((size_t)3 * N_NODES + row) * HID + 1];

    const size_t base = (size_t)row * 32 + lane;
    float4 S = __ldcs(((const float4*)g_SI) + base);
    float4 I = __ldcs(I4 + base);

    float4 dS, dI, dR;
    dS.x = -beta * AI.x * S.x;  dS.y = -beta * AI.y * S.y;
    dS.z = -beta * AI.z * S.z;  dS.w = -beta * AI.w * S.w;
    dI.x = -dS.x - gamma * I.x; dI.y = -dS.y - gamma * I.y;
    dI.z = -dS.z - gamma * I.z; dI.w = -dS.w - gamma * I.w;
    dR.x =  gamma * I.x;        dR.y =  gamma * I.y;
    dR.z =  gamma * I.z;        dR.w =  gamma * I.w;

    float4* o = (float4*)out;
    const size_t slab = (size_t)N_NODES * 32;
    __stcs(o + base,            dS);
    __stcs(o + slab + base,     dI);
    __stcs(o + 2 * slab + base, dR);
    __stcs(o + 3 * slab + base, make_float4(0.f, 0.f, 0.f, 0.f));
}

// ---------------------------------------------------------------------------
// Side stream + events, created at load time (outside any capture / mem
// checkpoint). Streams are not device-memory allocations.
// ---------------------------------------------------------------------------
namespace {
struct GraphResources {
    cudaStream_t s_sort = nullptr;
    cudaEvent_t  ev_fork = nullptr, ev_join = nullptr;
    GraphResources() {
        cudaStreamCreateWithFlags(&s_sort, cudaStreamNonBlocking);
        cudaEventCreateWithFlags(&ev_fork, cudaEventDisableTiming);
        cudaEventCreateWithFlags(&ev_join, cudaEventDisableTiming);
    }
};
GraphResources g_res;
}

// ---------------------------------------------------------------------------
extern "C" void kernel_launch(void* const* d_in, const int* in_sizes, int n_in,
                              void* d_out, int out_size) {
    const float* x    = (const float*)d_in[0];
    const float* W    = (const float*)d_in[1];
    const float* b    = (const float*)d_in[2];
    const int*   rows = (const int*)d_in[3];
    const int*   cols = (const int*)d_in[4];
    float*       out  = (float*)d_out;

    const int smem = (128 * WPAD + 2 * 128 * 128 + 128) * 4;   // 198144 B
    cudaFuncSetAttribute(gemm_persistent_kernel,
                         cudaFuncAttributeMaxDynamicSharedMemorySize, smem);

    cudaStream_t s1 = g_res.s_sort;

    // Fork: sort chain runs concurrently with the (FMA-bound) GEMM.
    cudaEventRecord(g_res.ev_fork, 0);
    cudaStreamWaitEvent(s1, g_res.ev_fork, 0);

    const int ebloks = (NE4 + 255) / 256;
    zero_cnt_kernel<<<NSCAN_BLOCKS, 1024, 0, s1>>>();
    hist_kernel<<<ebloks, 256, 0, s1>>>(rows);
    scan1_kernel<<<NSCAN_BLOCKS, 1024, 0, s1>>>();
    scan2_kernel<<<1, 128, 0, s1>>>();
    scan3_kernel<<<NSCAN_BLOCKS, 1024, 0, s1>>>();
    bucket_kernel<<<ebloks, 256, 0, s1>>>(rows, cols);
    cudaEventRecord(g_res.ev_join, s1);

    // Main stream: persistent GEMM.
    gemm_persistent_kernel<<<GEMM_GRID, 256, smem>>>(x, W, b);

    // Join: gather needs both GEMM (stream order) and sort (event).
    cudaStreamWaitEvent(0, g_res.ev_join, 0);
    gather_epilogue_kernel<<<(N_NODES + 7) / 8, 256>>>(x, out);
}

// round 10
// speedup vs baseline: 2.0266x; 1.3103x over previous
#include <cuda_runtime.h>
#include <cuda_bf16.h>
#include <cstdint>

#define N_NODES 100000
#define HID     128
#define N_EDGES 1600000
#define NSCAN_BLOCKS 98   // 98*1024 = 100352 >= N_NODES
#define NE4 (N_EDGES / 4) // 400000 int4 elements
#define TILES   782       // ceil(100000/128)
#define NJOBS   (2 * TILES)
#define GEMM_GRID 148
#define XPAD 132          // conflict-free tf32 fragment LDS

// Scratch (__device__ globals; no allocation allowed)
__device__ float g_SI[2u * N_NODES * HID];     // [0]=S, [1]=I  (102.4 MB)
__device__ int   g_cnt[N_NODES];               // histogram, then bucket cursor
__device__ int   g_start[N_NODES];             // exclusive prefix (row segment start)
__device__ int   g_blk[1024];                  // block sums for scan
__device__ int   g_scols[N_EDGES];             // cols sorted by destination row

__device__ __forceinline__ unsigned smem_u32(const void* p) {
    unsigned a;
    asm("{ .reg .u64 t; cvta.to.shared.u64 t, %1; cvt.u32.u64 %0, t; }"
        : "=r"(a) : "l"(p));
    return a;
}

__device__ __forceinline__ unsigned to_tf32(float f) {
    unsigned r;
    asm("cvt.rna.tf32.f32 %0, %1;" : "=r"(r) : "f"(f));
    return r;
}

__device__ __forceinline__ void mma_tf32(float* d, const unsigned* a,
                                         const unsigned* b) {
    asm volatile(
        "mma.sync.aligned.m16n8k8.row.col.f32.tf32.tf32.f32 "
        "{%0,%1,%2,%3}, {%4,%5,%6,%7}, {%8,%9}, {%0,%1,%2,%3};\n"
        : "+f"(d[0]), "+f"(d[1]), "+f"(d[2]), "+f"(d[3])
        : "r"(a[0]), "r"(a[1]), "r"(a[2]), "r"(a[3]), "r"(b[0]), "r"(b[1]));
}

// ---------------------------------------------------------------------------
// Persistent tf32 tensor-core GEMM: S/I = sigmoid(x[s] @ W^T + b), s in {0,1}
// 148 blocks loop over 128x128 tile-jobs. W (tf32-rounded) + b in SMEM once;
// X double-buffered via cp.async. 8 warps: warp tile 64(m) x 32(n).
// SMEM: Ws[128*132] + Xs0/Xs1[128*132] + Bs[128] = 203264 B.
// ---------------------------------------------------------------------------
__global__ void __launch_bounds__(256, 1)
gemm_tc_kernel(const float* __restrict__ x,
               const float* __restrict__ W,
               const float* __restrict__ b) {
    extern __shared__ float sm[];
    float* Ws  = sm;                          // 128*XPAD (tf32-rounded bits)
    float* Xs0 = sm + 128 * XPAD;
    float* Xs1 = Xs0 + 128 * XPAD;
    float* Bs  = Xs1 + 128 * XPAD;            // 128

    const int tid  = threadIdx.x;
    const int wid  = tid >> 5;
    const int lane = tid & 31;
    const int qrow = lane >> 2;    // 0..7
    const int qcol = lane & 3;     // 0..3
    const int warpM = wid & 1;     // 2 x 64 rows
    const int warpN = wid >> 1;    // 4 x 32 cols

    // W -> SMEM as Ws[c][k], pre-rounded to tf32. b -> Bs.
    for (int idx = tid; idx < 128 * 128; idx += 256) {
        int c = idx >> 7, k = idx & 127;
        Ws[c * XPAD + k] = __uint_as_float(to_tf32(W[idx]));
    }
    if (tid < 128) Bs[tid] = b[tid];

    // cp.async prefetch of one 128x128 X tile into padded SMEM rows.
    auto issue_tile = [&](int job, float* dst) {
        const int s    = (job >= TILES) ? 1 : 0;
        const int row0 = (job - s * TILES) * 128;
        const char* src = (const char*)(x + ((size_t)s * N_NODES + row0) * HID);
        unsigned d = smem_u32(dst);
#pragma unroll
        for (int i = 0; i < 16; i++) {
            int c   = tid + i * 256;       // 4096 16B chunks
            int row = c >> 5, col16 = c & 31;
            asm volatile("cp.async.cg.shared.global [%0], [%1], 16;"
                         :: "r"(d + (row * XPAD * 4 + col16 * 16)),
                            "l"(src + (size_t)row * 512 + col16 * 16)
                         : "memory");
        }
        asm volatile("cp.async.commit_group;" ::: "memory");
    };

    int job = blockIdx.x;
    if (job < NJOBS) issue_tile(job, Xs0);
    int buf = 0;

    for (; job < NJOBS; job += GEMM_GRID) {
        const int nxt = job + GEMM_GRID;
        float* Xc = buf ? Xs1 : Xs0;
        if (nxt < NJOBS) {
            issue_tile(nxt, buf ? Xs0 : Xs1);
            asm volatile("cp.async.wait_group 1;" ::: "memory");
        } else {
            asm volatile("cp.async.wait_group 0;" ::: "memory");
        }
        __syncthreads();

        float acc[4][4][4];
#pragma unroll
        for (int i = 0; i < 4; i++)
#pragma unroll
            for (int j = 0; j < 4; j++)
#pragma unroll
                for (int q = 0; q < 4; q++) acc[i][j][q] = 0.f;

#pragma unroll 2
        for (int k0 = 0; k0 < 128; k0 += 8) {
            unsigned af[4][4], bf[4][2];
#pragma unroll
            for (int i = 0; i < 4; i++) {
                const float* base = Xc + (warpM * 64 + i * 16 + qrow) * XPAD + k0 + qcol;
                af[i][0] = to_tf32(base[0]);
                af[i][1] = to_tf32(base[8 * XPAD]);
                af[i][2] = to_tf32(base[4]);
                af[i][3] = to_tf32(base[8 * XPAD + 4]);
            }
#pragma unroll
            for (int j = 0; j < 4; j++) {
                const float* base = Ws + (warpN * 32 + j * 8 + qrow) * XPAD + k0 + qcol;
                bf[j][0] = __float_as_uint(base[0]);
                bf[j][1] = __float_as_uint(base[4]);
            }
#pragma unroll
            for (int i = 0; i < 4; i++)
#pragma unroll
                for (int j = 0; j < 4; j++)
                    mma_tf32(acc[i][j], af[i], bf[j]);
        }

        const int s    = (job >= TILES) ? 1 : 0;
        const int row0 = (job - s * TILES) * 128;
        float* outS = g_SI + ((size_t)s * N_NODES + row0) * HID;
#pragma unroll
        for (int i = 0; i < 4; i++) {
            const int r0 = warpM * 64 + i * 16 + qrow;
#pragma unroll
            for (int j = 0; j < 4; j++) {
                const int c  = warpN * 32 + j * 8 + 2 * qcol;
                const float b0 = Bs[c], b1 = Bs[c + 1];
                if (row0 + r0 < N_NODES) {
                    float z0 = acc[i][j][0] + b0;
                    float z1 = acc[i][j][1] + b1;
                    float2 v = make_float2(1.f / (1.f + __expf(-z0)),
                                           1.f / (1.f + __expf(-z1)));
                    *(float2*)(outS + (size_t)r0 * HID + c) = v;
                }
                if (row0 + r0 + 8 < N_NODES) {
                    float z2 = acc[i][j][2] + b0;
                    float z3 = acc[i][j][3] + b1;
                    float2 v = make_float2(1.f / (1.f + __expf(-z2)),
                                           1.f / (1.f + __expf(-z3)));
                    *(float2*)(outS + (size_t)(r0 + 8) * HID + c) = v;
                }
            }
        }
        __syncthreads();     // protect Xc before refill
        buf ^= 1;
    }
}

// ---------------------------------------------------------------------------
// Counting sort of edges by destination row
// ---------------------------------------------------------------------------
__global__ void __launch_bounds__(1024) zero_cnt_kernel() {
    int i = blockIdx.x * 1024 + threadIdx.x;
    if (i < N_NODES) g_cnt[i] = 0;
}

__global__ void __launch_bounds__(256) hist_kernel(const int* __restrict__ rows) {
    int t = blockIdx.x * 256 + threadIdx.x;
    if (t >= NE4) return;
    int4 r = ((const int4*)rows)[t];
    atomicAdd(&g_cnt[r.x], 1);
    atomicAdd(&g_cnt[r.y], 1);
    atomicAdd(&g_cnt[r.z], 1);
    atomicAdd(&g_cnt[r.w], 1);
}

__global__ void __launch_bounds__(1024) scan1_kernel() {
    __shared__ int sh[1024];
    int tid = threadIdx.x;
    int i   = blockIdx.x * 1024 + tid;
    int v   = (i < N_NODES) ? g_cnt[i] : 0;
    sh[tid] = v;
    __syncthreads();
#pragma unroll
    for (int off = 1; off < 1024; off <<= 1) {
        int t = (tid >= off) ? sh[tid - off] : 0;
        __syncthreads();
        sh[tid] += t;
        __syncthreads();
    }
    if (i < N_NODES) g_start[i] = sh[tid] - v;   // exclusive
    if (tid == 1023) g_blk[blockIdx.x] = sh[1023];
}

__global__ void __launch_bounds__(128) scan2_kernel() {
    __shared__ int sh[128];
    int tid = threadIdx.x;
    int v   = (tid < NSCAN_BLOCKS) ? g_blk[tid] : 0;
    sh[tid] = v;
    __syncthreads();
#pragma unroll
    for (int off = 1; off < 128; off <<= 1) {
        int t = (tid >= off) ? sh[tid - off] : 0;
        __syncthreads();
        sh[tid] += t;
        __syncthreads();
    }
    g_blk[tid] = sh[tid] - v;   // exclusive
}

__global__ void __launch_bounds__(1024) scan3_kernel() {
    int i = blockIdx.x * 1024 + threadIdx.x;
    if (i < N_NODES) {
        int s = g_start[i] + g_blk[i >> 10];
        g_start[i] = s;
        g_cnt[i]   = s;          // bucket cursor
    }
}

__global__ void __launch_bounds__(256)
bucket_kernel(const int* __restrict__ rows, const int* __restrict__ cols) {
    int t = blockIdx.x * 256 + threadIdx.x;
    if (t >= NE4) return;
    int4 r = ((const int4*)rows)[t];
    int4 c = ((const int4*)cols)[t];
    int p0 = atomicAdd(&g_cnt[r.x], 1);
    int p1 = atomicAdd(&g_cnt[r.y], 1);
    int p2 = atomicAdd(&g_cnt[r.z], 1);
    int p3 = atomicAdd(&g_cnt[r.w], 1);
    g_scols[p0] = c.x;
    g_scols[p1] = c.y;
    g_scols[p2] = c.z;
    g_scols[p3] = c.w;
}

// ---------------------------------------------------------------------------
// Fused gather + epilogue: one warp per row (R5 form, proven fastest).
// ---------------------------------------------------------------------------
__global__ void __launch_bounds__(256)
gather_epilogue_kernel(const float* __restrict__ x, float* __restrict__ out) {
    const int warp = (blockIdx.x * 256 + threadIdx.x) >> 5;
    const int lane = threadIdx.x & 31;
    if (warp >= N_NODES) return;
    const int row = warp;

    const int s0 = g_start[row];
    const int s1 = (row + 1 < N_NODES) ? g_start[row + 1] : N_EDGES;

    const float4* I4 = (const float4*)(g_SI + (size_t)N_NODES * HID);
    float4 a0 = make_float4(0.f, 0.f, 0.f, 0.f);
    float4 a1 = make_float4(0.f, 0.f, 0.f, 0.f);

    int i = s0;
    for (; i + 1 < s1; i += 2) {
        int c0 = g_scols[i];
        int c1 = g_scols[i + 1];
        float4 v0 = I4[(size_t)c0 * 32 + lane];
        float4 v1 = I4[(size_t)c1 * 32 + lane];
        a0.x += v0.x; a0.y += v0.y; a0.z += v0.z; a0.w += v0.w;
        a1.x += v1.x; a1.y += v1.y; a1.z += v1.z; a1.w += v1.w;
    }
    if (i < s1) {
        int c0 = g_scols[i];
        float4 v0 = I4[(size_t)c0 * 32 + lane];
        a0.x += v0.x; a0.y += v0.y; a0.z += v0.z; a0.w += v0.w;
    }
    float4 AI;
    AI.x = a0.x + a1.x; AI.y = a0.y + a1.y;
    AI.z = a0.z + a1.z; AI.w = a0.w + a1.w;

    const float beta  = x[((size_t)3 * N_NODES + row) * HID + 0];
    const float gamma = x[((size_t)3 * N_NODES + row) * HID + 1];

    const size_t base = (size_t)row * 32 + lane;
    float4 S = __ldcs(((const float4*)g_SI) + base);
    float4 I = __ldcs(I4 + base);

    float4 dS, dI, dR;
    dS.x = -beta * AI.x * S.x;  dS.y = -beta * AI.y * S.y;
    dS.z = -beta * AI.z * S.z;  dS.w = -beta * AI.w * S.w;
    dI.x = -dS.x - gamma * I.x; dI.y = -dS.y - gamma * I.y;
    dI.z = -dS.z - gamma * I.z; dI.w = -dS.w - gamma * I.w;
    dR.x =  gamma * I.x;        dR.y =  gamma * I.y;
    dR.z =  gamma * I.z;        dR.w =  gamma * I.w;

    float4* o = (float4*)out;
    const size_t slab = (size_t)N_NODES * 32;
    __stcs(o + base,            dS);
    __stcs(o + slab + base,     dI);
    __stcs(o + 2 * slab + base, dR);
    __stcs(o + 3 * slab + base, make_float4(0.f, 0.f, 0.f, 0.f));
}

// ---------------------------------------------------------------------------
// Side stream + events, created at load time (outside capture / mem checks).
// ---------------------------------------------------------------------------
namespace {
struct GraphResources {
    cudaStream_t s_sort = nullptr;
    cudaEvent_t  ev_fork = nullptr, ev_join = nullptr;
    GraphResources() {
        cudaStreamCreateWithFlags(&s_sort, cudaStreamNonBlocking);
        cudaEventCreateWithFlags(&ev_fork, cudaEventDisableTiming);
        cudaEventCreateWithFlags(&ev_join, cudaEventDisableTiming);
    }
};
GraphResources g_res;
}

// ---------------------------------------------------------------------------
extern "C" void kernel_launch(void* const* d_in, const int* in_sizes, int n_in,
                              void* d_out, int out_size) {
    const float* x    = (const float*)d_in[0];
    const float* W    = (const float*)d_in[1];
    const float* b    = (const float*)d_in[2];
    const int*   rows = (const int*)d_in[3];
    const int*   cols = (const int*)d_in[4];
    float*       out  = (float*)d_out;

    const int smem = (3 * 128 * XPAD + 128) * 4;   // 203264 B
    cudaFuncSetAttribute(gemm_tc_kernel,
                         cudaFuncAttributeMaxDynamicSharedMemorySize, smem);

    cudaStream_t s1 = g_res.s_sort;

    // Fork: sort chain runs concurrently with the tensor-core GEMM.
    cudaEventRecord(g_res.ev_fork, 0);
    cudaStreamWaitEvent(s1, g_res.ev_fork, 0);

    const int ebloks = (NE4 + 255) / 256;
    zero_cnt_kernel<<<NSCAN_BLOCKS, 1024, 0, s1>>>();
    hist_kernel<<<ebloks, 256, 0, s1>>>(rows);
    scan1_kernel<<<NSCAN_BLOCKS, 1024, 0, s1>>>();
    scan2_kernel<<<1, 128, 0, s1>>>();
    scan3_kernel<<<NSCAN_BLOCKS, 1024, 0, s1>>>();
    bucket_kernel<<<ebloks, 256, 0, s1>>>(rows, cols);
    cudaEventRecord(g_res.ev_join, s1);

    // Main stream: persistent tf32 tensor-core GEMM.
    gemm_tc_kernel<<<GEMM_GRID, 256, smem>>>(x, W, b);

    // Join: gather needs both GEMM (stream order) and sort (event).
    cudaStreamWaitEvent(0, g_res.ev_join, 0);
    gather_epilogue_kernel<<<(N_NODES + 7) / 8, 256>>>(x, out);
}

// round 11
// speedup vs baseline: 2.1461x; 1.0589x over previous
#include <cuda_runtime.h>
#include <cuda_bf16.h>
#include <cstdint>

#define N_NODES 100000
#define HID     128
#define N_EDGES 1600000
#define NSCAN_BLOCKS 98   // 98*1024 = 100352 >= N_NODES
#define NE4 (N_EDGES / 4) // 400000 int4 elements
#define TILES   782       // ceil(100000/128)
#define NJOBS   (2 * TILES)
#define GEMM_GRID 148
#define XPAD 132          // conflict-free tf32 fragment LDS

// Scratch (__device__ globals; no allocation allowed)
__device__ float          g_SI[2u * N_NODES * HID];   // [0]=S, [1]=I (fp32)
__device__ __nv_bfloat16  g_Ibf[(size_t)N_NODES * HID]; // bf16 mirror of I (25.6MB)
__device__ int   g_cnt[N_NODES];               // histogram, then bucket cursor
__device__ int   g_start[N_NODES];             // exclusive prefix (segment start)
__device__ int   g_blk[1024];                  // block sums for scan
__device__ int   g_scols[N_EDGES];             // cols sorted by destination row

__device__ __forceinline__ unsigned smem_u32(const void* p) {
    unsigned a;
    asm("{ .reg .u64 t; cvta.to.shared.u64 t, %1; cvt.u32.u64 %0, t; }"
        : "=r"(a) : "l"(p));
    return a;
}

__device__ __forceinline__ unsigned to_tf32(float f) {
    unsigned r;
    asm("cvt.rna.tf32.f32 %0, %1;" : "=r"(r) : "f"(f));
    return r;
}

__device__ __forceinline__ void mma_tf32(float* d, const unsigned* a,
                                         const unsigned* b) {
    asm volatile(
        "mma.sync.aligned.m16n8k8.row.col.f32.tf32.tf32.f32 "
        "{%0,%1,%2,%3}, {%4,%5,%6,%7}, {%8,%9}, {%0,%1,%2,%3};\n"
        : "+f"(d[0]), "+f"(d[1]), "+f"(d[2]), "+f"(d[3])
        : "r"(a[0]), "r"(a[1]), "r"(a[2]), "r"(a[3]), "r"(b[0]), "r"(b[1]));
}

// ---------------------------------------------------------------------------
// Persistent tf32 tensor-core GEMM: S/I = sigmoid(x[s] @ W^T + b), s in {0,1}
// s=1 additionally mirrors I to bf16 (gather operand).
// ---------------------------------------------------------------------------
__global__ void __launch_bounds__(256, 1)
gemm_tc_kernel(const float* __restrict__ x,
               const float* __restrict__ W,
               const float* __restrict__ b) {
    extern __shared__ float sm[];
    float* Ws  = sm;                          // 128*XPAD (tf32-rounded bits)
    float* Xs0 = sm + 128 * XPAD;
    float* Xs1 = Xs0 + 128 * XPAD;
    float* Bs  = Xs1 + 128 * XPAD;            // 128

    const int tid  = threadIdx.x;
    const int wid  = tid >> 5;
    const int lane = tid & 31;
    const int qrow = lane >> 2;    // 0..7
    const int qcol = lane & 3;     // 0..3
    const int warpM = wid & 1;     // 2 x 64 rows
    const int warpN = wid >> 1;    // 4 x 32 cols

    for (int idx = tid; idx < 128 * 128; idx += 256) {
        int c = idx >> 7, k = idx & 127;
        Ws[c * XPAD + k] = __uint_as_float(to_tf32(W[idx]));
    }
    if (tid < 128) Bs[tid] = b[tid];

    auto issue_tile = [&](int job, float* dst) {
        const int s    = (job >= TILES) ? 1 : 0;
        const int row0 = (job - s * TILES) * 128;
        const char* src = (const char*)(x + ((size_t)s * N_NODES + row0) * HID);
        unsigned d = smem_u32(dst);
#pragma unroll
        for (int i = 0; i < 16; i++) {
            int c   = tid + i * 256;       // 4096 16B chunks
            int row = c >> 5, col16 = c & 31;
            asm volatile("cp.async.cg.shared.global [%0], [%1], 16;"
                         :: "r"(d + (row * XPAD * 4 + col16 * 16)),
                            "l"(src + (size_t)row * 512 + col16 * 16)
                         : "memory");
        }
        asm volatile("cp.async.commit_group;" ::: "memory");
    };

    int job = blockIdx.x;
    if (job < NJOBS) issue_tile(job, Xs0);
    int buf = 0;

    for (; job < NJOBS; job += GEMM_GRID) {
        const int nxt = job + GEMM_GRID;
        float* Xc = buf ? Xs1 : Xs0;
        if (nxt < NJOBS) {
            issue_tile(nxt, buf ? Xs0 : Xs1);
            asm volatile("cp.async.wait_group 1;" ::: "memory");
        } else {
            asm volatile("cp.async.wait_group 0;" ::: "memory");
        }
        __syncthreads();

        float acc[4][4][4];
#pragma unroll
        for (int i = 0; i < 4; i++)
#pragma unroll
            for (int j = 0; j < 4; j++)
#pragma unroll
                for (int q = 0; q < 4; q++) acc[i][j][q] = 0.f;

#pragma unroll 2
        for (int k0 = 0; k0 < 128; k0 += 8) {
            unsigned af[4][4], bf[4][2];
#pragma unroll
            for (int i = 0; i < 4; i++) {
                const float* base = Xc + (warpM * 64 + i * 16 + qrow) * XPAD + k0 + qcol;
                af[i][0] = to_tf32(base[0]);
                af[i][1] = to_tf32(base[8 * XPAD]);
                af[i][2] = to_tf32(base[4]);
                af[i][3] = to_tf32(base[8 * XPAD + 4]);
            }
#pragma unroll
            for (int j = 0; j < 4; j++) {
                const float* base = Ws + (warpN * 32 + j * 8 + qrow) * XPAD + k0 + qcol;
                bf[j][0] = __float_as_uint(base[0]);
                bf[j][1] = __float_as_uint(base[4]);
            }
#pragma unroll
            for (int i = 0; i < 4; i++)
#pragma unroll
                for (int j = 0; j < 4; j++)
                    mma_tf32(acc[i][j], af[i], bf[j]);
        }

        const int s    = (job >= TILES) ? 1 : 0;
        const int row0 = (job - s * TILES) * 128;
        float* outS = g_SI + ((size_t)s * N_NODES + row0) * HID;
        __nv_bfloat16* outB = g_Ibf + (size_t)row0 * HID;
#pragma unroll
        for (int i = 0; i < 4; i++) {
            const int r0 = warpM * 64 + i * 16 + qrow;
#pragma unroll
            for (int j = 0; j < 4; j++) {
                const int c  = warpN * 32 + j * 8 + 2 * qcol;
                const float b0 = Bs[c], b1 = Bs[c + 1];
                if (row0 + r0 < N_NODES) {
                    float2 v = make_float2(
                        1.f / (1.f + __expf(-(acc[i][j][0] + b0))),
                        1.f / (1.f + __expf(-(acc[i][j][1] + b1))));
                    *(float2*)(outS + (size_t)r0 * HID + c) = v;
                    if (s)
                        *(__nv_bfloat162*)(outB + (size_t)r0 * HID + c) =
                            __float22bfloat162_rn(v);
                }
                if (row0 + r0 + 8 < N_NODES) {
                    float2 v = make_float2(
                        1.f / (1.f + __expf(-(acc[i][j][2] + b0))),
                        1.f / (1.f + __expf(-(acc[i][j][3] + b1))));
                    *(float2*)(outS + (size_t)(r0 + 8) * HID + c) = v;
                    if (s)
                        *(__nv_bfloat162*)(outB + (size_t)(r0 + 8) * HID + c) =
                            __float22bfloat162_rn(v);
                }
            }
        }
        __syncthreads();
        buf ^= 1;
    }
}

// ---------------------------------------------------------------------------
// Counting sort of edges by destination row
// ---------------------------------------------------------------------------
__global__ void __launch_bounds__(1024) zero_cnt_kernel() {
    int i = blockIdx.x * 1024 + threadIdx.x;
    if (i < N_NODES) g_cnt[i] = 0;
}

__global__ void __launch_bounds__(256) hist_kernel(const int* __restrict__ rows) {
    int t = blockIdx.x * 256 + threadIdx.x;
    if (t >= NE4) return;
    int4 r = ((const int4*)rows)[t];
    atomicAdd(&g_cnt[r.x], 1);
    atomicAdd(&g_cnt[r.y], 1);
    atomicAdd(&g_cnt[r.z], 1);
    atomicAdd(&g_cnt[r.w], 1);
}

__global__ void __launch_bounds__(1024) scan1_kernel() {
    __shared__ int sh[1024];
    int tid = threadIdx.x;
    int i   = blockIdx.x * 1024 + tid;
    int v   = (i < N_NODES) ? g_cnt[i] : 0;
    sh[tid] = v;
    __syncthreads();
#pragma unroll
    for (int off = 1; off < 1024; off <<= 1) {
        int t = (tid >= off) ? sh[tid - off] : 0;
        __syncthreads();
        sh[tid] += t;
        __syncthreads();
    }
    if (i < N_NODES) g_start[i] = sh[tid] - v;   // exclusive
    if (tid == 1023) g_blk[blockIdx.x] = sh[1023];
}

__global__ void __launch_bounds__(128) scan2_kernel() {
    __shared__ int sh[128];
    int tid = threadIdx.x;
    int v   = (tid < NSCAN_BLOCKS) ? g_blk[tid] : 0;
    sh[tid] = v;
    __syncthreads();
#pragma unroll
    for (int off = 1; off < 128; off <<= 1) {
        int t = (tid >= off) ? sh[tid - off] : 0;
        __syncthreads();
        sh[tid] += t;
        __syncthreads();
    }
    g_blk[tid] = sh[tid] - v;   // exclusive
}

__global__ void __launch_bounds__(1024) scan3_kernel() {
    int i = blockIdx.x * 1024 + threadIdx.x;
    if (i < N_NODES) {
        int s = g_start[i] + g_blk[i >> 10];
        g_start[i] = s;
        g_cnt[i]   = s;          // bucket cursor
    }
}

__global__ void __launch_bounds__(256)
bucket_kernel(const int* __restrict__ rows, const int* __restrict__ cols) {
    int t = blockIdx.x * 256 + threadIdx.x;
    if (t >= NE4) return;
    int4 r = ((const int4*)rows)[t];
    int4 c = ((const int4*)cols)[t];
    int p0 = atomicAdd(&g_cnt[r.x], 1);
    int p1 = atomicAdd(&g_cnt[r.y], 1);
    int p2 = atomicAdd(&g_cnt[r.z], 1);
    int p3 = atomicAdd(&g_cnt[r.w], 1);
    g_scols[p0] = c.x;
    g_scols[p1] = c.y;
    g_scols[p2] = c.z;
    g_scols[p3] = c.w;
}

// ---------------------------------------------------------------------------
// Fused gather + epilogue: one warp per row; bf16 gather operand (256B/edge).
// ---------------------------------------------------------------------------
__global__ void __launch_bounds__(256)
gather_epilogue_kernel(const float* __restrict__ x, float* __restrict__ out) {
    const int warp = (blockIdx.x * 256 + threadIdx.x) >> 5;
    const int lane = threadIdx.x & 31;
    if (warp >= N_NODES) return;
    const int row = warp;

    const int s0 = g_start[row];
    const int s1 = (row + 1 < N_NODES) ? g_start[row + 1] : N_EDGES;

    const uint2* Ib = (const uint2*)g_Ibf;   // 32 uint2 per node row
    float4 a0 = make_float4(0.f, 0.f, 0.f, 0.f);
    float4 a1 = make_float4(0.f, 0.f, 0.f, 0.f);

    int i = s0;
    for (; i + 1 < s1; i += 2) {
        int c0 = g_scols[i];
        int c1 = g_scols[i + 1];
        uint2 u0 = Ib[(size_t)c0 * 32 + lane];
        uint2 u1 = Ib[(size_t)c1 * 32 + lane];
        float2 f00 = __bfloat1622float2(*(__nv_bfloat162*)&u0.x);
        float2 f01 = __bfloat1622float2(*(__nv_bfloat162*)&u0.y);
        float2 f10 = __bfloat1622float2(*(__nv_bfloat162*)&u1.x);
        float2 f11 = __bfloat1622float2(*(__nv_bfloat162*)&u1.y);
        a0.x += f00.x; a0.y += f00.y; a0.z += f01.x; a0.w += f01.y;
        a1.x += f10.x; a1.y += f10.y; a1.z += f11.x; a1.w += f11.y;
    }
    if (i < s1) {
        int c0 = g_scols[i];
        uint2 u0 = Ib[(size_t)c0 * 32 + lane];
        float2 f00 = __bfloat1622float2(*(__nv_bfloat162*)&u0.x);
        float2 f01 = __bfloat1622float2(*(__nv_bfloat162*)&u0.y);
        a0.x += f00.x; a0.y += f00.y; a0.z += f01.x; a0.w += f01.y;
    }
    float4 AI;
    AI.x = a0.x + a1.x; AI.y = a0.y + a1.y;
    AI.z = a0.z + a1.z; AI.w = a0.w + a1.w;

    const float beta  = x[((size_t)3 * N_NODES + row) * HID + 0];
    const float gamma = x[((size_t)3 * N_NODES + row) * HID + 1];

    const size_t base = (size_t)row * 32 + lane;
    const float4* I4 = (const float4*)(g_SI + (size_t)N_NODES * HID);
    float4 S = __ldcs(((const float4*)g_SI) + base);
    float4 I = __ldcs(I4 + base);

    float4 dS, dI, dR;
    dS.x = -beta * AI.x * S.x;  dS.y = -beta * AI.y * S.y;
    dS.z = -beta * AI.z * S.z;  dS.w = -beta * AI.w * S.w;
    dI.x = -dS.x - gamma * I.x; dI.y = -dS.y - gamma * I.y;
    dI.z = -dS.z - gamma * I.z; dI.w = -dS.w - gamma * I.w;
    dR.x =  gamma * I.x;        dR.y =  gamma * I.y;
    dR.z =  gamma * I.z;        dR.w =  gamma * I.w;

    float4* o = (float4*)out;
    const size_t slab = (size_t)N_NODES * 32;
    __stcs(o + base,            dS);
    __stcs(o + slab + base,     dI);
    __stcs(o + 2 * slab + base, dR);
    __stcs(o + 3 * slab + base, make_float4(0.f, 0.f, 0.f, 0.f));
}

// ---------------------------------------------------------------------------
// Side stream + events, created at load time (outside capture / mem checks).
// ---------------------------------------------------------------------------
namespace {
struct GraphResources {
    cudaStream_t s_sort = nullptr;
    cudaEvent_t  ev_fork = nullptr, ev_join = nullptr;
    GraphResources() {
        cudaStreamCreateWithFlags(&s_sort, cudaStreamNonBlocking);
        cudaEventCreateWithFlags(&ev_fork, cudaEventDisableTiming);
        cudaEventCreateWithFlags(&ev_join, cudaEventDisableTiming);
    }
};
GraphResources g_res;
}

// ---------------------------------------------------------------------------
extern "C" void kernel_launch(void* const* d_in, const int* in_sizes, int n_in,
                              void* d_out, int out_size) {
    const float* x    = (const float*)d_in[0];
    const float* W    = (const float*)d_in[1];
    const float* b    = (const float*)d_in[2];
    const int*   rows = (const int*)d_in[3];
    const int*   cols = (const int*)d_in[4];
    float*       out  = (float*)d_out;

    const int smem = (3 * 128 * XPAD + 128) * 4;   // 203264 B
    cudaFuncSetAttribute(gemm_tc_kernel,
                         cudaFuncAttributeMaxDynamicSharedMemorySize, smem);

    cudaStream_t s1 = g_res.s_sort;

    // Fork: sort chain runs concurrently with the tensor-core GEMM.
    cudaEventRecord(g_res.ev_fork, 0);
    cudaStreamWaitEvent(s1, g_res.ev_fork, 0);

    const int ebloks = (NE4 + 255) / 256;
    zero_cnt_kernel<<<NSCAN_BLOCKS, 1024, 0, s1>>>();
    hist_kernel<<<ebloks, 256, 0, s1>>>(rows);
    scan1_kernel<<<NSCAN_BLOCKS, 1024, 0, s1>>>();
    scan2_kernel<<<1, 128, 0, s1>>>();
    scan3_kernel<<<NSCAN_BLOCKS, 1024, 0, s1>>>();
    bucket_kernel<<<ebloks, 256, 0, s1>>>(rows, cols);
    cudaEventRecord(g_res.ev_join, s1);

    // Main stream: persistent tf32 tensor-core GEMM (+ bf16 I mirror).
    gemm_tc_kernel<<<GEMM_GRID, 256, smem>>>(x, W, b);

    // Join: gather needs both GEMM (stream order) and sort (event).
    cudaStreamWaitEvent(0, g_res.ev_join, 0);
    gather_epilogue_kernel<<<(N_NODES + 7) / 8, 256>>>(x, out);
}

// round 12
// speedup vs baseline: 2.2018x; 1.0260x over previous
#include <cuda_runtime.h>
#include <cuda_bf16.h>
#include <cstdint>

#define N_NODES 100000
#define HID     128
#define N_EDGES 1600000
#define SCAN_BLOCKS 98    // 98*1024 = 100352 >= N_NODES
#define NE4 (N_EDGES / 4) // 400000 int4 elements
#define TILES   782       // ceil(100000/128)
#define NJOBS   (2 * TILES)
#define GEMM_GRID 148
#define XPAD 132          // conflict-free tf32 fragment LDS

// Scratch (__device__ globals; zero-initialized at module load; no allocs)
__device__ float          g_SI[2u * N_NODES * HID];     // [0]=S, [1]=I (fp32)
__device__ __nv_bfloat16  g_Ibf[(size_t)N_NODES * HID]; // bf16 mirror of I
__device__ int   g_cnt[N_NODES];               // histogram, then bucket cursor
__device__ int   g_start[N_NODES];             // exclusive prefix (segment start)
__device__ unsigned long long g_tile[SCAN_BLOCKS]; // lookback: (flag<<32)|value
__device__ int   g_scols[N_EDGES];             // cols sorted by destination row

__device__ __forceinline__ unsigned smem_u32(const void* p) {
    unsigned a;
    asm("{ .reg .u64 t; cvta.to.shared.u64 t, %1; cvt.u32.u64 %0, t; }"
        : "=r"(a) : "l"(p));
    return a;
}

__device__ __forceinline__ unsigned to_tf32(float f) {
    unsigned r;
    asm("cvt.rna.tf32.f32 %0, %1;" : "=r"(r) : "f"(f));
    return r;
}

__device__ __forceinline__ void mma_tf32(float* d, const unsigned* a,
                                         const unsigned* b) {
    asm volatile(
        "mma.sync.aligned.m16n8k8.row.col.f32.tf32.tf32.f32 "
        "{%0,%1,%2,%3}, {%4,%5,%6,%7}, {%8,%9}, {%0,%1,%2,%3};\n"
        : "+f"(d[0]), "+f"(d[1]), "+f"(d[2]), "+f"(d[3])
        : "r"(a[0]), "r"(a[1]), "r"(a[2]), "r"(a[3]), "r"(b[0]), "r"(b[1]));
}

// ---------------------------------------------------------------------------
// Persistent tf32 tensor-core GEMM: S/I = sigmoid(x[s] @ W^T + b), s in {0,1}
// s=1 additionally mirrors I to bf16 (gather operand).
// ---------------------------------------------------------------------------
__global__ void __launch_bounds__(256, 1)
gemm_tc_kernel(const float* __restrict__ x,
               const float* __restrict__ W,
               const float* __restrict__ b) {
    extern __shared__ float sm[];
    float* Ws  = sm;                          // 128*XPAD (tf32-rounded bits)
    float* Xs0 = sm + 128 * XPAD;
    float* Xs1 = Xs0 + 128 * XPAD;
    float* Bs  = Xs1 + 128 * XPAD;            // 128

    const int tid  = threadIdx.x;
    const int wid  = tid >> 5;
    const int lane = tid & 31;
    const int qrow = lane >> 2;    // 0..7
    const int qcol = lane & 3;     // 0..3
    const int warpM = wid & 1;     // 2 x 64 rows
    const int warpN = wid >> 1;    // 4 x 32 cols

    for (int idx = tid; idx < 128 * 128; idx += 256) {
        int c = idx >> 7, k = idx & 127;
        Ws[c * XPAD + k] = __uint_as_float(to_tf32(W[idx]));
    }
    if (tid < 128) Bs[tid] = b[tid];

    auto issue_tile = [&](int job, float* dst) {
        const int s    = (job >= TILES) ? 1 : 0;
        const int row0 = (job - s * TILES) * 128;
        const char* src = (const char*)(x + ((size_t)s * N_NODES + row0) * HID);
        unsigned d = smem_u32(dst);
#pragma unroll
        for (int i = 0; i < 16; i++) {
            int c   = tid + i * 256;       // 4096 16B chunks
            int row = c >> 5, col16 = c & 31;
            asm volatile("cp.async.cg.shared.global [%0], [%1], 16;"
                         :: "r"(d + (row * XPAD * 4 + col16 * 16)),
                            "l"(src + (size_t)row * 512 + col16 * 16)
                         : "memory");
        }
        asm volatile("cp.async.commit_group;" ::: "memory");
    };

    int job = blockIdx.x;
    if (job < NJOBS) issue_tile(job, Xs0);
    int buf = 0;

    for (; job < NJOBS; job += GEMM_GRID) {
        const int nxt = job + GEMM_GRID;
        float* Xc = buf ? Xs1 : Xs0;
        if (nxt < NJOBS) {
            issue_tile(nxt, buf ? Xs0 : Xs1);
            asm volatile("cp.async.wait_group 1;" ::: "memory");
        } else {
            asm volatile("cp.async.wait_group 0;" ::: "memory");
        }
        __syncthreads();

        float acc[4][4][4];
#pragma unroll
        for (int i = 0; i < 4; i++)
#pragma unroll
            for (int j = 0; j < 4; j++)
#pragma unroll
                for (int q = 0; q < 4; q++) acc[i][j][q] = 0.f;

#pragma unroll 2
        for (int k0 = 0; k0 < 128; k0 += 8) {
            unsigned af[4][4], bf[4][2];
#pragma unroll
            for (int i = 0; i < 4; i++) {
                const float* base = Xc + (warpM * 64 + i * 16 + qrow) * XPAD + k0 + qcol;
                af[i][0] = to_tf32(base[0]);
                af[i][1] = to_tf32(base[8 * XPAD]);
                af[i][2] = to_tf32(base[4]);
                af[i][3] = to_tf32(base[8 * XPAD + 4]);
            }
#pragma unroll
            for (int j = 0; j < 4; j++) {
                const float* base = Ws + (warpN * 32 + j * 8 + qrow) * XPAD + k0 + qcol;
                bf[j][0] = __float_as_uint(base[0]);
                bf[j][1] = __float_as_uint(base[4]);
            }
#pragma unroll
            for (int i = 0; i < 4; i++)
#pragma unroll
                for (int j = 0; j < 4; j++)
                    mma_tf32(acc[i][j], af[i], bf[j]);
        }

        const int s    = (job >= TILES) ? 1 : 0;
        const int row0 = (job - s * TILES) * 128;
        float* outS = g_SI + ((size_t)s * N_NODES + row0) * HID;
        __nv_bfloat16* outB = g_Ibf + (size_t)row0 * HID;
#pragma unroll
        for (int i = 0; i < 4; i++) {
            const int r0 = warpM * 64 + i * 16 + qrow;
#pragma unroll
            for (int j = 0; j < 4; j++) {
                const int c  = warpN * 32 + j * 8 + 2 * qcol;
                const float b0 = Bs[c], b1 = Bs[c + 1];
                if (row0 + r0 < N_NODES) {
                    float2 v = make_float2(
                        1.f / (1.f + __expf(-(acc[i][j][0] + b0))),
                        1.f / (1.f + __expf(-(acc[i][j][1] + b1))));
                    *(float2*)(outS + (size_t)r0 * HID + c) = v;
                    if (s)
                        *(__nv_bfloat162*)(outB + (size_t)r0 * HID + c) =
                            __float22bfloat162_rn(v);
                }
                if (row0 + r0 + 8 < N_NODES) {
                    float2 v = make_float2(
                        1.f / (1.f + __expf(-(acc[i][j][2] + b0))),
                        1.f / (1.f + __expf(-(acc[i][j][3] + b1))));
                    *(float2*)(outS + (size_t)(r0 + 8) * HID + c) = v;
                    if (s)
                        *(__nv_bfloat162*)(outB + (size_t)(r0 + 8) * HID + c) =
                            __float22bfloat162_rn(v);
                }
            }
        }
        __syncthreads();
        buf ^= 1;
    }
}

// ---------------------------------------------------------------------------
// Counting sort of edges by destination row.
// g_cnt arrives zeroed (module-load zero-init on call 1; gather resets it
// at the end of every launch thereafter).
// ---------------------------------------------------------------------------
__global__ void __launch_bounds__(256) hist_kernel(const int* __restrict__ rows) {
    int t = blockIdx.x * 256 + threadIdx.x;
    if (t >= NE4) return;
    int4 r = ((const int4*)rows)[t];
    atomicAdd(&g_cnt[r.x], 1);
    atomicAdd(&g_cnt[r.y], 1);
    atomicAdd(&g_cnt[r.z], 1);
    atomicAdd(&g_cnt[r.w], 1);
}

// Single-kernel exclusive scan over 100K bins: per-block smem scan +
// decoupled lookback via one 64-bit word/block ((flag<<32)|value, flag:
// 1=aggregate, 2=inclusive-prefix). All 98 blocks are co-resident.
// g_tile arrives zeroed (reset by gather each launch).
__global__ void __launch_bounds__(1024) scan_fused_kernel() {
    __shared__ int sh[1024];
    __shared__ int s_prefix;
    const int tid = threadIdx.x;
    const int bid = blockIdx.x;
    const int i   = bid * 1024 + tid;
    const int v   = (i < N_NODES) ? g_cnt[i] : 0;
    sh[tid] = v;
    __syncthreads();
#pragma unroll
    for (int off = 1; off < 1024; off <<= 1) {
        int t = (tid >= off) ? sh[tid - off] : 0;
        __syncthreads();
        sh[tid] += t;
        __syncthreads();
    }
    const int incl     = sh[tid];
    const int blocksum = sh[1023];

    if (tid == 0) {
        if (bid == 0) {
            atomicExch(&g_tile[0], (2ull << 32) | (unsigned)blocksum);
            s_prefix = 0;
        } else {
            atomicExch(&g_tile[bid], (1ull << 32) | (unsigned)blocksum);
            int run = 0;
            int j = bid - 1;
            while (true) {
                unsigned long long t;
                do { t = atomicAdd(&g_tile[j], 0ull); } while ((t >> 32) == 0);
                run += (int)(unsigned)t;
                if ((t >> 32) == 2ull) break;
                j--;
            }
            atomicExch(&g_tile[bid], (2ull << 32) | (unsigned)(run + blocksum));
            s_prefix = run;
        }
    }
    __syncthreads();

    if (i < N_NODES) {
        int excl = incl - v + s_prefix;
        g_start[i] = excl;
        g_cnt[i]   = excl;     // bucket cursor
    }
}

__global__ void __launch_bounds__(256)
bucket_kernel(const int* __restrict__ rows, const int* __restrict__ cols) {
    int t = blockIdx.x * 256 + threadIdx.x;
    if (t >= NE4) return;
    int4 r = ((const int4*)rows)[t];
    int4 c = ((const int4*)cols)[t];
    int p0 = atomicAdd(&g_cnt[r.x], 1);
    int p1 = atomicAdd(&g_cnt[r.y], 1);
    int p2 = atomicAdd(&g_cnt[r.z], 1);
    int p3 = atomicAdd(&g_cnt[r.w], 1);
    g_scols[p0] = c.x;
    g_scols[p1] = c.y;
    g_scols[p2] = c.z;
    g_scols[p3] = c.w;
}

// ---------------------------------------------------------------------------
// slab3 (all-zeros output plane), done on its own stream under the overlap.
// ---------------------------------------------------------------------------
__global__ void __launch_bounds__(256)
zero_slab3_kernel(float* __restrict__ out) {
    size_t idx = (size_t)blockIdx.x * 256 + threadIdx.x;   // N*32 float4
    __stcs(((float4*)out) + 3 * (size_t)N_NODES * 32 + idx,
           make_float4(0.f, 0.f, 0.f, 0.f));
}

// ---------------------------------------------------------------------------
// Fused gather + epilogue: one warp per row; bf16 gather operand (256B/edge).
// Also resets g_cnt / g_tile so the next graph replay sees zeroed state.
// ---------------------------------------------------------------------------
__global__ void __launch_bounds__(256)
gather_epilogue_kernel(const float* __restrict__ x, float* __restrict__ out) {
    if (blockIdx.x == 0 && threadIdx.x < SCAN_BLOCKS)
        g_tile[threadIdx.x] = 0ull;

    const int warp = (blockIdx.x * 256 + threadIdx.x) >> 5;
    const int lane = threadIdx.x & 31;
    if (warp >= N_NODES) return;
    const int row = warp;

    const int s0 = g_start[row];
    const int s1 = (row + 1 < N_NODES) ? g_start[row + 1] : N_EDGES;
    if (lane == 0) g_cnt[row] = 0;     // reset histogram for next launch

    const uint2* Ib = (const uint2*)g_Ibf;   // 32 uint2 per node row
    float4 a0 = make_float4(0.f, 0.f, 0.f, 0.f);
    float4 a1 = make_float4(0.f, 0.f, 0.f, 0.f);

    int i = s0;
    for (; i + 1 < s1; i += 2) {
        int c0 = g_scols[i];
        int c1 = g_scols[i + 1];
        uint2 u0 = Ib[(size_t)c0 * 32 + lane];
        uint2 u1 = Ib[(size_t)c1 * 32 + lane];
        float2 f00 = __bfloat1622float2(*(__nv_bfloat162*)&u0.x);
        float2 f01 = __bfloat1622float2(*(__nv_bfloat162*)&u0.y);
        float2 f10 = __bfloat1622float2(*(__nv_bfloat162*)&u1.x);
        float2 f11 = __bfloat1622float2(*(__nv_bfloat162*)&u1.y);
        a0.x += f00.x; a0.y += f00.y; a0.z += f01.x; a0.w += f01.y;
        a1.x += f10.x; a1.y += f10.y; a1.z += f11.x; a1.w += f11.y;
    }
    if (i < s1) {
        int c0 = g_scols[i];
        uint2 u0 = Ib[(size_t)c0 * 32 + lane];
        float2 f00 = __bfloat1622float2(*(__nv_bfloat162*)&u0.x);
        float2 f01 = __bfloat1622float2(*(__nv_bfloat162*)&u0.y);
        a0.x += f00.x; a0.y += f00.y; a0.z += f01.x; a0.w += f01.y;
    }
    float4 AI;
    AI.x = a0.x + a1.x; AI.y = a0.y + a1.y;
    AI.z = a0.z + a1.z; AI.w = a0.w + a1.w;

    const float beta  = x[((size_t)3 * N_NODES + row) * HID + 0];
    const float gamma = x[((size_t)3 * N_NODES + row) * HID + 1];

    const size_t base = (size_t)row * 32 + lane;
    const float4* I4 = (const float4*)(g_SI + (size_t)N_NODES * HID);
    float4 S = __ldcs(((const float4*)g_SI) + base);
    float4 I = __ldcs(I4 + base);

    float4 dS, dI, dR;
    dS.x = -beta * AI.x * S.x;  dS.y = -beta * AI.y * S.y;
    dS.z = -beta * AI.z * S.z;  dS.w = -beta * AI.w * S.w;
    dI.x = -dS.x - gamma * I.x; dI.y = -dS.y - gamma * I.y;
    dI.z = -dS.z - gamma * I.z; dI.w = -dS.w - gamma * I.w;
    dR.x =  gamma * I.x;        dR.y =  gamma * I.y;
    dR.z =  gamma * I.z;        dR.w =  gamma * I.w;

    float4* o = (float4*)out;
    const size_t slab = (size_t)N_NODES * 32;
    __stcs(o + base,            dS);
    __stcs(o + slab + base,     dI);
    __stcs(o + 2 * slab + base, dR);
}

// ---------------------------------------------------------------------------
// Streams + events, created at load time (outside capture / mem checks).
// ---------------------------------------------------------------------------
namespace {
struct GraphResources {
    cudaStream_t s_sort = nullptr, s_zero = nullptr;
    cudaEvent_t  ev_fork = nullptr, ev_join = nullptr, ev_zero = nullptr;
    GraphResources() {
        int lo = 0, hi = 0;
        cudaDeviceGetStreamPriorityRange(&lo, &hi);   // hi = highest prio
        cudaStreamCreateWithPriority(&s_sort, cudaStreamNonBlocking, hi);
        cudaStreamCreateWithFlags(&s_zero, cudaStreamNonBlocking);
        cudaEventCreateWithFlags(&ev_fork, cudaEventDisableTiming);
        cudaEventCreateWithFlags(&ev_join, cudaEventDisableTiming);
        cudaEventCreateWithFlags(&ev_zero, cudaEventDisableTiming);
    }
};
GraphResources g_res;
}

// ---------------------------------------------------------------------------
extern "C" void kernel_launch(void* const* d_in, const int* in_sizes, int n_in,
                              void* d_out, int out_size) {
    const float* x    = (const float*)d_in[0];
    const float* W    = (const float*)d_in[1];
    const float* b    = (const float*)d_in[2];
    const int*   rows = (const int*)d_in[3];
    const int*   cols = (const int*)d_in[4];
    float*       out  = (float*)d_out;

    const int smem = (3 * 128 * XPAD + 128) * 4;   // 203264 B
    cudaFuncSetAttribute(gemm_tc_kernel,
                         cudaFuncAttributeMaxDynamicSharedMemorySize, smem);

    cudaStream_t s1 = g_res.s_sort;
    cudaStream_t s2 = g_res.s_zero;

    // Fork.
    cudaEventRecord(g_res.ev_fork, 0);
    cudaStreamWaitEvent(s1, g_res.ev_fork, 0);
    cudaStreamWaitEvent(s2, g_res.ev_fork, 0);

    // s2: zero the all-zeros output plane under the overlap window.
    zero_slab3_kernel<<<(N_NODES * 32 + 255) / 256, 256, 0, s2>>>(out);
    cudaEventRecord(g_res.ev_zero, s2);

    // s1: counting sort (hist -> fused scan -> bucket).
    const int ebloks = (NE4 + 255) / 256;
    hist_kernel<<<ebloks, 256, 0, s1>>>(rows);
    scan_fused_kernel<<<SCAN_BLOCKS, 1024, 0, s1>>>();
    bucket_kernel<<<ebloks, 256, 0, s1>>>(rows, cols);
    cudaEventRecord(g_res.ev_join, s1);

    // Main stream: persistent tf32 tensor-core GEMM (+ bf16 I mirror).
    gemm_tc_kernel<<<GEMM_GRID, 256, smem>>>(x, W, b);

    // Join: gather needs GEMM (stream order), sort and slab3 (events).
    cudaStreamWaitEvent(0, g_res.ev_join, 0);
    cudaStreamWaitEvent(0, g_res.ev_zero, 0);
    gather_epilogue_kernel<<<(N_NODES + 7) / 8, 256>>>(x, out);
}